// round 2
// baseline (speedup 1.0000x reference)
#include <cuda_runtime.h>

#define NMAX  100000
#define EMAX  3200000
#define INF   128
#define HID   50
#define PITCH 52
#define KC    16

// ---------------- static device scratch (no allocs allowed) ----------------
__device__ int    g_is64;
__device__ int    g_cnt[NMAX];
__device__ int    g_off[NMAX + 1];
__device__ int    g_wcur[NMAX];
__device__ int    g_bsum[128];
__device__ int    g_src[EMAX];
__device__ int    g_dst[EMAX];
__device__ int    g_csrc[EMAX];
__device__ float  g_cnorm[EMAX];
__device__ float  g_dinv[NMAX];
__device__ float  g_h1[(size_t)NMAX * PITCH];
__device__ float2 g_z[NMAX];

// ---------------- dtype sniff: int64 edge data has zero high words -----------
__global__ void k_detect(const unsigned int* __restrict__ p) {
    __shared__ int nz;
    int t = threadIdx.x;
    if (t == 0) nz = 0;
    __syncthreads();
    if (p[2 * t + 1] != 0u) atomicOr(&nz, 1);
    __syncthreads();
    if (t == 0) g_is64 = nz ? 0 : 1;   // all-zero odd words -> int64 layout
}

// ---------------- build: count degrees, split edge index ----------------
__global__ void k_zero(int N) {
    int i = blockIdx.x * blockDim.x + threadIdx.x;
    if (i < N) g_cnt[i] = 0;
}

__global__ void k_prep(const void* __restrict__ eiv, int E) {
    int i = blockIdx.x * blockDim.x + threadIdx.x;
    if (i >= E) return;
    int s, d;
    if (g_is64) {
        const long long* p = (const long long*)eiv;
        s = (int)p[i];
        d = (int)p[(size_t)E + i];
    } else {
        const int* p = (const int*)eiv;
        s = p[i];
        d = p[(size_t)E + i];
    }
    g_src[i] = s;
    g_dst[i] = d;
    atomicAdd(&g_cnt[d], 1);
}

// ---------------- 3-kernel exclusive scan over g_cnt -> g_off ----------------
__global__ void k_scan1(int N) {
    __shared__ int sh[1024];
    int t = threadIdx.x;
    int i = blockIdx.x * 1024 + t;
    int v = (i < N) ? g_cnt[i] : 0;
    sh[t] = v;
    __syncthreads();
    for (int o = 1; o < 1024; o <<= 1) {
        int x = (t >= o) ? sh[t - o] : 0;
        __syncthreads();
        sh[t] += x;
        __syncthreads();
    }
    if (i < N) g_off[i] = sh[t] - v;          // exclusive, pre-base
    if (t == 1023) g_bsum[blockIdx.x] = sh[1023];
}

__global__ void k_scan2(int NB) {
    __shared__ int sh[128];
    int t = threadIdx.x;
    int v = (t < NB) ? g_bsum[t] : 0;
    sh[t] = v;
    __syncthreads();
    for (int o = 1; o < 128; o <<= 1) {
        int x = (t >= o) ? sh[t - o] : 0;
        __syncthreads();
        sh[t] += x;
        __syncthreads();
    }
    if (t < NB) g_bsum[t] = sh[t] - v;        // exclusive block base
}

__global__ void k_scan3(int N, int E) {
    int t = threadIdx.x;
    int i = blockIdx.x * 1024 + t;
    if (i >= N) return;
    int off = g_off[i] + g_bsum[blockIdx.x];
    g_off[i]  = off;
    g_wcur[i] = off;
    g_dinv[i] = rsqrtf((float)(g_cnt[i] + 1));  // +1 = self loop
    if (i == 0) g_off[N] = E;
}

// ---------------- CSR bucket fill (int atomics on cursors only) ----------------
__global__ void k_fill(int E) {
    int i = blockIdx.x * blockDim.x + threadIdx.x;
    if (i >= E) return;
    int d = g_dst[i];
    int s = g_src[i];
    int pos = atomicAdd(&g_wcur[d], 1);
    g_csrc[pos]  = s;
    g_cnorm[pos] = g_dinv[s] * g_dinv[d];
}

// ---------------- GEMM1: h1 = x @ W1  (100000x128 @ 128x50, pad->52) ----------
// block = 128 threads, tile = 128 nodes x 52 outputs
// thread owns 4 nodes x 13 outputs
__global__ void k_gemm1(const float* __restrict__ x, const float* __restrict__ W1, int N) {
    __shared__ float xs[128][KC + 1];
    __shared__ float Ws[KC][PITCH];
    int tid   = threadIdx.x;
    int node0 = blockIdx.x * 128;
    int jg = tid & 3;        // 4 j-groups of 13
    int ng = tid >> 2;       // 32 node-groups of 4

    float acc[4][13];
#pragma unroll
    for (int m = 0; m < 4; m++)
#pragma unroll
        for (int jj = 0; jj < 13; jj++) acc[m][jj] = 0.f;

    for (int k0 = 0; k0 < INF; k0 += KC) {
        // stage W chunk (zero-pad cols 50,51)
        for (int i = tid; i < KC * PITCH; i += 128) {
            int kk = i / PITCH, j = i % PITCH;
            Ws[kk][j] = (j < HID) ? W1[(k0 + kk) * HID + j] : 0.f;
        }
        // stage x chunk: 128 rows x KC cols
#pragma unroll
        for (int r = 0; r < 4; r++) {
            int idx = tid + r * 128;
            int row = idx >> 2, c4 = idx & 3;
            int node = node0 + row;
            float4 v = make_float4(0.f, 0.f, 0.f, 0.f);
            if (node < N)
                v = *(const float4*)(x + (size_t)node * INF + k0 + c4 * 4);
            xs[row][c4 * 4 + 0] = v.x;
            xs[row][c4 * 4 + 1] = v.y;
            xs[row][c4 * 4 + 2] = v.z;
            xs[row][c4 * 4 + 3] = v.w;
        }
        __syncthreads();
#pragma unroll
        for (int kk = 0; kk < KC; kk++) {
            float xm[4];
#pragma unroll
            for (int m = 0; m < 4; m++) xm[m] = xs[ng * 4 + m][kk];
            float wv[13];
#pragma unroll
            for (int jj = 0; jj < 13; jj++) wv[jj] = Ws[kk][jg * 13 + jj];
#pragma unroll
            for (int m = 0; m < 4; m++)
#pragma unroll
                for (int jj = 0; jj < 13; jj++) acc[m][jj] += xm[m] * wv[jj];
        }
        __syncthreads();
    }
#pragma unroll
    for (int m = 0; m < 4; m++) {
        int node = node0 + ng * 4 + m;
        if (node < N) {
#pragma unroll
            for (int jj = 0; jj < 13; jj++)
                g_h1[(size_t)node * PITCH + jg * 13 + jj] = acc[m][jj];
        }
    }
}

// ---------------- layer-1 aggregation + bias + relu + tiny GEMM (W2) ---------
// warp per node; lane l (<25) owns feature pair (2l, 2l+1) via one float2 load
__global__ void k_agg1(const float* __restrict__ b1, const float* __restrict__ W2, int N) {
    int gt = blockIdx.x * blockDim.x + threadIdx.x;
    int i = gt >> 5, lane = gt & 31;
    if (i >= N) return;

    float dii = g_dinv[i];
    float sw  = dii * dii;
    int beg = g_off[i], end = g_off[i + 1];

    bool act = lane < 25;
    int  f   = lane * 2;
    float ax = 0.f, ay = 0.f;
    if (act) {
        float2 v = *(const float2*)(g_h1 + (size_t)i * PITCH + f);
        ax = v.x * sw;
        ay = v.y * sw;
    }
    for (int e = beg; e < end; e++) {
        int   s  = g_csrc[e];
        float nr = g_cnorm[e];
        if (act) {
            float2 v = *(const float2*)(g_h1 + (size_t)s * PITCH + f);
            ax += v.x * nr;
            ay += v.y * nr;
        }
    }
    float z0 = 0.f, z1 = 0.f;
    if (act) {
        float hx = fmaxf(ax + b1[f], 0.f);
        float hy = fmaxf(ay + b1[f + 1], 0.f);
        z0 = hx * W2[f * 2 + 0] + hy * W2[(f + 1) * 2 + 0];
        z1 = hx * W2[f * 2 + 1] + hy * W2[(f + 1) * 2 + 1];
    }
#pragma unroll
    for (int o = 16; o; o >>= 1) {
        z0 += __shfl_xor_sync(0xffffffffu, z0, o);
        z1 += __shfl_xor_sync(0xffffffffu, z1, o);
    }
    if (lane == 0) g_z[i] = make_float2(z0, z1);
}

// ---------------- layer-2 aggregation + bias + log_softmax -------------------
__global__ void k_agg2(const float* __restrict__ b2, float* __restrict__ out, int N) {
    int gt = blockIdx.x * blockDim.x + threadIdx.x;
    int i = gt >> 5, lane = gt & 31;
    if (i >= N) return;

    int beg = g_off[i], end = g_off[i + 1];
    float a0 = 0.f, a1 = 0.f;
    for (int e = beg + lane; e < end; e += 32) {
        int   s  = g_csrc[e];
        float nr = g_cnorm[e];
        float2 zv = g_z[s];
        a0 += zv.x * nr;
        a1 += zv.y * nr;
    }
#pragma unroll
    for (int o = 16; o; o >>= 1) {
        a0 += __shfl_xor_sync(0xffffffffu, a0, o);
        a1 += __shfl_xor_sync(0xffffffffu, a1, o);
    }
    if (lane == 0) {
        float dii = g_dinv[i];
        float sw  = dii * dii;
        float2 zi = g_z[i];
        float o0 = a0 + zi.x * sw + b2[0];
        float o1 = a1 + zi.y * sw + b2[1];
        float m   = fmaxf(o0, o1);
        float lse = m + log1pf(expf(fminf(o0, o1) - m));
        out[2 * i + 0] = o0 - lse;
        out[2 * i + 1] = o1 - lse;
    }
}

// ---------------- launch ----------------
extern "C" void kernel_launch(void* const* d_in, const int* in_sizes, int n_in,
                              void* d_out, int out_size) {
    const float* x  = (const float*)d_in[0];
    const void*  ei = (const void*)d_in[1];
    const float* W1 = (const float*)d_in[2];
    const float* b1 = (const float*)d_in[3];
    const float* W2 = (const float*)d_in[4];
    const float* b2 = (const float*)d_in[5];
    float*       out = (float*)d_out;

    int N = in_sizes[0] / INF;
    int E = in_sizes[1] / 2;
    if (N > NMAX) N = NMAX;
    if (E > EMAX) E = EMAX;
    int NB = (N + 1023) / 1024;

    k_detect<<<1, 256>>>((const unsigned int*)ei);
    k_zero<<<NB, 1024>>>(N);
    k_prep<<<(E + 255) / 256, 256>>>(ei, E);
    k_scan1<<<NB, 1024>>>(N);
    k_scan2<<<1, 128>>>(NB);
    k_scan3<<<NB, 1024>>>(N, E);
    k_fill<<<(E + 255) / 256, 256>>>(E);
    k_gemm1<<<(N + 127) / 128, 128>>>(x, W1, N);
    int agg_blocks = (N * 32 + 255) / 256;
    k_agg1<<<agg_blocks, 256>>>(b1, W2, N);
    k_agg2<<<agg_blocks, 256>>>(b2, out, N);
}

// round 3
// speedup vs baseline: 1.0472x; 1.0472x over previous
#include <cuda_runtime.h>
#include <cuda_fp16.h>

#define NMAX  100000
#define EMAX  3200000
#define INF   128
#define HID   50
#define PITCH 52
#define KC    16

// ---------------- static device scratch ----------------
__device__ int    g_is64;
__device__ int    g_cnt[NMAX];
__device__ int    g_off[NMAX + 1];
__device__ int    g_wcur[NMAX];
__device__ int    g_bsum[128];
__device__ int    g_csrc[EMAX];
__device__ float  g_dinv[NMAX];
__device__ __half g_h1h[(size_t)NMAX * PITCH];   // fp16, pre-scaled by dinv[row]
__device__ float2 g_z[NMAX];                     // z' = dinv * (h @ W2)

// ---------------- init: zero counts + dtype sniff ----------------
__global__ void k_init(const unsigned int* __restrict__ p, int N) {
    int i = blockIdx.x * blockDim.x + threadIdx.x;
    if (i < N) g_cnt[i] = 0;
    if (blockIdx.x == 0) {
        __shared__ int nz;
        int t = threadIdx.x;
        if (t == 0) nz = 0;
        __syncthreads();
        if (t < 256 && p[2 * t + 1] != 0u) atomicOr(&nz, 1);
        __syncthreads();
        if (t == 0) g_is64 = nz ? 0 : 1;   // all-zero odd words -> int64 layout
    }
}

// ---------------- count degrees (dst half only) ----------------
__global__ void k_prep(const void* __restrict__ eiv, int E) {
    int i = blockIdx.x * blockDim.x + threadIdx.x;
    if (i >= E) return;
    int d;
    if (g_is64) d = (int)((const long long*)eiv)[(size_t)E + i];
    else        d = ((const int*)eiv)[(size_t)E + i];
    atomicAdd(&g_cnt[d], 1);
}

// ---------------- warp-shuffle exclusive scan ----------------
__global__ void k_scan1(int N) {
    __shared__ int wsum[32];
    int t = threadIdx.x;
    int i = blockIdx.x * 1024 + t;
    int v = (i < N) ? g_cnt[i] : 0;
    int x = v;
#pragma unroll
    for (int o = 1; o < 32; o <<= 1) {
        int y = __shfl_up_sync(0xffffffffu, x, o);
        if ((t & 31) >= o) x += y;
    }
    if ((t & 31) == 31) wsum[t >> 5] = x;
    __syncthreads();
    if (t < 32) {
        int w = wsum[t], xx = w;
#pragma unroll
        for (int o = 1; o < 32; o <<= 1) {
            int y = __shfl_up_sync(0xffffffffu, xx, o);
            if (t >= o) xx += y;
        }
        wsum[t] = xx - w;   // exclusive warp base
    }
    __syncthreads();
    int incl = x + wsum[t >> 5];
    if (i < N) g_off[i] = incl - v;           // exclusive, pre-base
    if (t == 1023) g_bsum[blockIdx.x] = incl;
}

__global__ void k_scan2(int NB) {
    int t = threadIdx.x;
    __shared__ int wsum[4];
    int v = (t < NB) ? g_bsum[t] : 0;
    int x = v;
#pragma unroll
    for (int o = 1; o < 32; o <<= 1) {
        int y = __shfl_up_sync(0xffffffffu, x, o);
        if ((t & 31) >= o) x += y;
    }
    if ((t & 31) == 31) wsum[t >> 5] = x;
    __syncthreads();
    int base = 0;
    for (int w = 0; w < (t >> 5); w++) base += wsum[w];
    if (t < NB) g_bsum[t] = base + x - v;     // exclusive block base
}

__global__ void k_scan3(int N, int E) {
    int t = threadIdx.x;
    int i = blockIdx.x * 1024 + t;
    if (i >= N) return;
    int off = g_off[i] + g_bsum[blockIdx.x];
    g_off[i]  = off;
    g_wcur[i] = off;
    g_dinv[i] = rsqrtf((float)(g_cnt[i] + 1));  // +1 = self loop
    if (i == 0) g_off[N] = E;
}

// ---------------- CSR fill: src index only (norm folded into h1') ------------
__global__ void k_fill(const void* __restrict__ eiv, int E) {
    int i = blockIdx.x * blockDim.x + threadIdx.x;
    if (i >= E) return;
    int s, d;
    if (g_is64) {
        const long long* p = (const long long*)eiv;
        s = (int)p[i];
        d = (int)p[(size_t)E + i];
    } else {
        const int* p = (const int*)eiv;
        s = p[i];
        d = p[(size_t)E + i];
    }
    int pos = atomicAdd(&g_wcur[d], 1);
    g_csrc[pos] = s;
}

// ---------------- GEMM1: h1' = dinv * (x @ W1), stored fp16 ------------------
__global__ void k_gemm1(const float* __restrict__ x, const float* __restrict__ W1, int N) {
    __shared__ float xs[128][KC + 1];
    __shared__ float Ws[KC][PITCH];
    int tid   = threadIdx.x;
    int node0 = blockIdx.x * 128;
    int jg = tid & 3;        // 4 j-groups of 13
    int ng = tid >> 2;       // 32 node-groups of 4

    float acc[4][13];
#pragma unroll
    for (int m = 0; m < 4; m++)
#pragma unroll
        for (int jj = 0; jj < 13; jj++) acc[m][jj] = 0.f;

    for (int k0 = 0; k0 < INF; k0 += KC) {
        for (int i = tid; i < KC * PITCH; i += 128) {
            int kk = i / PITCH, j = i % PITCH;
            Ws[kk][j] = (j < HID) ? W1[(k0 + kk) * HID + j] : 0.f;
        }
#pragma unroll
        for (int r = 0; r < 4; r++) {
            int idx = tid + r * 128;
            int row = idx >> 2, c4 = idx & 3;
            int node = node0 + row;
            float4 v = make_float4(0.f, 0.f, 0.f, 0.f);
            if (node < N)
                v = *(const float4*)(x + (size_t)node * INF + k0 + c4 * 4);
            xs[row][c4 * 4 + 0] = v.x;
            xs[row][c4 * 4 + 1] = v.y;
            xs[row][c4 * 4 + 2] = v.z;
            xs[row][c4 * 4 + 3] = v.w;
        }
        __syncthreads();
#pragma unroll
        for (int kk = 0; kk < KC; kk++) {
            float xm[4];
#pragma unroll
            for (int m = 0; m < 4; m++) xm[m] = xs[ng * 4 + m][kk];
            float wv[13];
#pragma unroll
            for (int jj = 0; jj < 13; jj++) wv[jj] = Ws[kk][jg * 13 + jj];
#pragma unroll
            for (int m = 0; m < 4; m++)
#pragma unroll
                for (int jj = 0; jj < 13; jj++) acc[m][jj] += xm[m] * wv[jj];
        }
        __syncthreads();
    }
#pragma unroll
    for (int m = 0; m < 4; m++) {
        int node = node0 + ng * 4 + m;
        if (node < N) {
            float di = g_dinv[node];
#pragma unroll
            for (int jj = 0; jj < 13; jj++)
                g_h1h[(size_t)node * PITCH + jg * 13 + jj] = __float2half(acc[m][jj] * di);
        }
    }
}

// ---------------- layer-1 agg + bias + relu + W2, emit z' = dinv*(h@W2) ------
__global__ void k_agg1(const float* __restrict__ b1, const float* __restrict__ W2, int N) {
    int gt = blockIdx.x * blockDim.x + threadIdx.x;
    int i = gt >> 5, lane = gt & 31;
    if (i >= N) return;

    float dii = g_dinv[i];
    int beg = g_off[i], end = g_off[i + 1];

    bool act = lane < 25;
    int  f   = lane * 2;
    float ax = 0.f, ay = 0.f;
    if (act) {
        float2 v = __half22float2(*(const __half2*)(g_h1h + (size_t)i * PITCH + f));
        ax = v.x; ay = v.y;                    // self term: h1'[i]
    }
    for (int e0 = beg; e0 < end; e0 += 32) {
        int sE = (e0 + lane < end) ? g_csrc[e0 + lane] : 0;
        int cnt = end - e0; if (cnt > 32) cnt = 32;
        for (int j = 0; j < cnt; j++) {
            int s = __shfl_sync(0xffffffffu, sE, j);
            if (act) {
                float2 v = __half22float2(*(const __half2*)(g_h1h + (size_t)s * PITCH + f));
                ax += v.x; ay += v.y;
            }
        }
    }
    float z0 = 0.f, z1 = 0.f;
    if (act) {
        float2 bb = *(const float2*)(b1 + f);
        float hx = fmaxf(fmaf(ax, dii, bb.x), 0.f);
        float hy = fmaxf(fmaf(ay, dii, bb.y), 0.f);
        float4 w = *(const float4*)(W2 + 2 * f);
        z0 = hx * w.x + hy * w.z;
        z1 = hx * w.y + hy * w.w;
    }
#pragma unroll
    for (int o = 16; o; o >>= 1) {
        z0 += __shfl_xor_sync(0xffffffffu, z0, o);
        z1 += __shfl_xor_sync(0xffffffffu, z1, o);
    }
    if (lane == 0) g_z[i] = make_float2(z0 * dii, z1 * dii);   // z'
}

// ---------------- layer-2 agg + bias + log_softmax ---------------------------
__global__ void k_agg2(const float* __restrict__ b2, float* __restrict__ out, int N) {
    int gt = blockIdx.x * blockDim.x + threadIdx.x;
    int i = gt >> 5, lane = gt & 31;
    if (i >= N) return;

    int beg = g_off[i], end = g_off[i + 1];
    float a0 = 0.f, a1 = 0.f;
    for (int e = beg + lane; e < end; e += 32) {
        float2 zv = g_z[g_csrc[e]];
        a0 += zv.x;
        a1 += zv.y;
    }
#pragma unroll
    for (int o = 16; o; o >>= 1) {
        a0 += __shfl_xor_sync(0xffffffffu, a0, o);
        a1 += __shfl_xor_sync(0xffffffffu, a1, o);
    }
    if (lane == 0) {
        float dii = g_dinv[i];
        float2 zi = g_z[i];
        float o0 = fmaf(a0 + zi.x, dii, b2[0]);
        float o1 = fmaf(a1 + zi.y, dii, b2[1]);
        float m   = fmaxf(o0, o1);
        float lse = m + log1pf(expf(fminf(o0, o1) - m));
        out[2 * i + 0] = o0 - lse;
        out[2 * i + 1] = o1 - lse;
    }
}

// ---------------- launch ----------------
extern "C" void kernel_launch(void* const* d_in, const int* in_sizes, int n_in,
                              void* d_out, int out_size) {
    const float* x  = (const float*)d_in[0];
    const void*  ei = (const void*)d_in[1];
    const float* W1 = (const float*)d_in[2];
    const float* b1 = (const float*)d_in[3];
    const float* W2 = (const float*)d_in[4];
    const float* b2 = (const float*)d_in[5];
    float*       out = (float*)d_out;

    int N = in_sizes[0] / INF;
    int E = in_sizes[1] / 2;
    if (N > NMAX) N = NMAX;
    if (E > EMAX) E = EMAX;
    int NB = (N + 1023) / 1024;

    k_init<<<NB, 1024>>>((const unsigned int*)ei, N);
    k_prep<<<(E + 255) / 256, 256>>>(ei, E);
    k_scan1<<<NB, 1024>>>(N);
    k_scan2<<<1, 128>>>(NB);
    k_scan3<<<NB, 1024>>>(N, E);
    k_fill<<<(E + 255) / 256, 256>>>(ei, E);
    k_gemm1<<<(N + 127) / 128, 128>>>(x, W1, N);
    int agg_blocks = (N * 32 + 255) / 256;
    k_agg1<<<agg_blocks, 256>>>(b1, W2, N);
    k_agg2<<<agg_blocks, 256>>>(b2, out, N);
}

// round 4
// speedup vs baseline: 1.1851x; 1.1316x over previous
#include <cuda_runtime.h>
#include <cuda_fp16.h>

#define NMAX  100000
#define EMAX  3200000
#define INF   128
#define HID   50
#define PITCH 52
#define KC    16

// ---------------- static device scratch ----------------
__device__ int    g_is64;
__device__ int    g_cnt[NMAX];
__device__ int    g_off[NMAX + 1];
__device__ int    g_wcur[NMAX];
__device__ int    g_bsum[128];
__device__ int    g_csrc[EMAX];
__device__ float  g_dinv[NMAX];
__device__ __half g_h1h[(size_t)NMAX * PITCH];   // fp16, UNSCALED x@W1
__device__ float2 g_z[NMAX];                     // z' = dinv * (h @ W2)

// ---------------- dtype sniff ----------------
__global__ void k_sniff(const unsigned int* __restrict__ p) {
    __shared__ int nz;
    int t = threadIdx.x;
    if (t == 0) nz = 0;
    __syncthreads();
    if (p[2 * t + 1] != 0u) atomicOr(&nz, 1);
    __syncthreads();
    if (t == 0) g_is64 = nz ? 0 : 1;
}

// ---------------- count degrees (dst half only) ----------------
__global__ void k_prep(const void* __restrict__ eiv, int E) {
    int i = blockIdx.x * blockDim.x + threadIdx.x;
    if (i >= E) return;
    int d;
    if (g_is64) d = (int)((const long long*)eiv)[(size_t)E + i];
    else        d = ((const int*)eiv)[(size_t)E + i];
    atomicAdd(&g_cnt[d], 1);
}

// ---------------- warp-shuffle exclusive scan ----------------
__global__ void k_scan1(int N) {
    __shared__ int wsum[32];
    int t = threadIdx.x;
    int i = blockIdx.x * 1024 + t;
    int v = (i < N) ? g_cnt[i] : 0;
    int x = v;
#pragma unroll
    for (int o = 1; o < 32; o <<= 1) {
        int y = __shfl_up_sync(0xffffffffu, x, o);
        if ((t & 31) >= o) x += y;
    }
    if ((t & 31) == 31) wsum[t >> 5] = x;
    __syncthreads();
    if (t < 32) {
        int w = wsum[t], xx = w;
#pragma unroll
        for (int o = 1; o < 32; o <<= 1) {
            int y = __shfl_up_sync(0xffffffffu, xx, o);
            if (t >= o) xx += y;
        }
        wsum[t] = xx - w;
    }
    __syncthreads();
    int incl = x + wsum[t >> 5];
    if (i < N) g_off[i] = incl - v;
    if (t == 1023) g_bsum[blockIdx.x] = incl;
}

__global__ void k_scan2(int NB) {
    int t = threadIdx.x;
    __shared__ int wsum[4];
    int v = (t < NB) ? g_bsum[t] : 0;
    int x = v;
#pragma unroll
    for (int o = 1; o < 32; o <<= 1) {
        int y = __shfl_up_sync(0xffffffffu, x, o);
        if ((t & 31) >= o) x += y;
    }
    if ((t & 31) == 31) wsum[t >> 5] = x;
    __syncthreads();
    int base = 0;
    for (int w = 0; w < (t >> 5); w++) base += wsum[w];
    if (t < NB) g_bsum[t] = base + x - v;
}

__global__ void k_scan3(int N, int E) {
    int t = threadIdx.x;
    int i = blockIdx.x * 1024 + t;
    if (i >= N) return;
    int off = g_off[i] + g_bsum[blockIdx.x];
    g_off[i]  = off;
    g_wcur[i] = off;
    g_dinv[i] = rsqrtf((float)(g_cnt[i] + 1));
    if (i == 0) g_off[N] = E;
}

// ---------------- CSR fill ----------------
__global__ void k_fill(const void* __restrict__ eiv, int E) {
    int i = blockIdx.x * blockDim.x + threadIdx.x;
    if (i >= E) return;
    int s, d;
    if (g_is64) {
        const long long* p = (const long long*)eiv;
        s = (int)p[i];
        d = (int)p[(size_t)E + i];
    } else {
        const int* p = (const int*)eiv;
        s = p[i];
        d = p[(size_t)E + i];
    }
    int pos = atomicAdd(&g_wcur[d], 1);
    g_csrc[pos] = s;
}

// ---------------- GEMM1: h1 = x @ W1, fp16, UNSCALED (input-only dep) --------
__global__ void k_gemm1(const float* __restrict__ x, const float* __restrict__ W1, int N) {
    __shared__ float xs[128][KC + 1];
    __shared__ float Ws[KC][PITCH];
    int tid   = threadIdx.x;
    int node0 = blockIdx.x * 128;
    int jg = tid & 3;
    int ng = tid >> 2;

    float acc[4][13];
#pragma unroll
    for (int m = 0; m < 4; m++)
#pragma unroll
        for (int jj = 0; jj < 13; jj++) acc[m][jj] = 0.f;

    for (int k0 = 0; k0 < INF; k0 += KC) {
        for (int i = tid; i < KC * PITCH; i += 128) {
            int kk = i / PITCH, j = i % PITCH;
            Ws[kk][j] = (j < HID) ? W1[(k0 + kk) * HID + j] : 0.f;
        }
#pragma unroll
        for (int r = 0; r < 4; r++) {
            int idx = tid + r * 128;
            int row = idx >> 2, c4 = idx & 3;
            int node = node0 + row;
            float4 v = make_float4(0.f, 0.f, 0.f, 0.f);
            if (node < N)
                v = *(const float4*)(x + (size_t)node * INF + k0 + c4 * 4);
            xs[row][c4 * 4 + 0] = v.x;
            xs[row][c4 * 4 + 1] = v.y;
            xs[row][c4 * 4 + 2] = v.z;
            xs[row][c4 * 4 + 3] = v.w;
        }
        __syncthreads();
#pragma unroll
        for (int kk = 0; kk < KC; kk++) {
            float xm[4];
#pragma unroll
            for (int m = 0; m < 4; m++) xm[m] = xs[ng * 4 + m][kk];
            float wv[13];
#pragma unroll
            for (int jj = 0; jj < 13; jj++) wv[jj] = Ws[kk][jg * 13 + jj];
#pragma unroll
            for (int m = 0; m < 4; m++)
#pragma unroll
                for (int jj = 0; jj < 13; jj++) acc[m][jj] += xm[m] * wv[jj];
        }
        __syncthreads();
    }
#pragma unroll
    for (int m = 0; m < 4; m++) {
        int node = node0 + ng * 4 + m;
        if (node < N) {
#pragma unroll
            for (int jj = 0; jj < 13; jj++)
                g_h1h[(size_t)node * PITCH + jg * 13 + jj] = __float2half(acc[m][jj]);
        }
    }
}

// ---------------- layer-1 agg (unroll x4, uniform idx loads) -----------------
__global__ void k_agg1(const float* __restrict__ b1, const float* __restrict__ W2, int N) {
    int gt = blockIdx.x * blockDim.x + threadIdx.x;
    int i = gt >> 5, lane = gt & 31;
    if (i >= N) return;

    float dii = g_dinv[i];
    int beg = g_off[i], end = g_off[i + 1];

    bool act = lane < 25;
    int  f   = lane * 2;
    const __half* hbase = g_h1h;
    float ax = 0.f, ay = 0.f;
    if (act) {
        float2 v = __half22float2(*(const __half2*)(hbase + (size_t)i * PITCH + f));
        ax = v.x * dii; ay = v.y * dii;     // self term dii*h_i
    }
    int e = beg;
    for (; e + 4 <= end; e += 4) {
        int s0 = g_csrc[e + 0];
        int s1 = g_csrc[e + 1];
        int s2 = g_csrc[e + 2];
        int s3 = g_csrc[e + 3];
        float d0 = g_dinv[s0], d1 = g_dinv[s1], d2 = g_dinv[s2], d3 = g_dinv[s3];
        if (act) {
            float2 v0 = __half22float2(*(const __half2*)(hbase + (size_t)s0 * PITCH + f));
            float2 v1 = __half22float2(*(const __half2*)(hbase + (size_t)s1 * PITCH + f));
            float2 v2 = __half22float2(*(const __half2*)(hbase + (size_t)s2 * PITCH + f));
            float2 v3 = __half22float2(*(const __half2*)(hbase + (size_t)s3 * PITCH + f));
            ax += d0 * v0.x + d1 * v1.x + d2 * v2.x + d3 * v3.x;
            ay += d0 * v0.y + d1 * v1.y + d2 * v2.y + d3 * v3.y;
        }
    }
    for (; e < end; e++) {
        int s0 = g_csrc[e];
        float d0 = g_dinv[s0];
        if (act) {
            float2 v0 = __half22float2(*(const __half2*)(hbase + (size_t)s0 * PITCH + f));
            ax += d0 * v0.x;
            ay += d0 * v0.y;
        }
    }
    float z0 = 0.f, z1 = 0.f;
    if (act) {
        float2 bb = *(const float2*)(b1 + f);
        float hx = fmaxf(fmaf(ax, dii, bb.x), 0.f);
        float hy = fmaxf(fmaf(ay, dii, bb.y), 0.f);
        float4 w = *(const float4*)(W2 + 2 * f);
        z0 = hx * w.x + hy * w.z;
        z1 = hx * w.y + hy * w.w;
    }
#pragma unroll
    for (int o = 16; o; o >>= 1) {
        z0 += __shfl_xor_sync(0xffffffffu, z0, o);
        z1 += __shfl_xor_sync(0xffffffffu, z1, o);
    }
    if (lane == 0) g_z[i] = make_float2(z0 * dii, z1 * dii);
}

// ---------------- layer-2 agg + log_softmax ----------------------------------
__global__ void k_agg2(const float* __restrict__ b2, float* __restrict__ out, int N) {
    int gt = blockIdx.x * blockDim.x + threadIdx.x;
    int i = gt >> 5, lane = gt & 31;
    if (i >= N) return;

    int beg = g_off[i], end = g_off[i + 1];
    float a0 = 0.f, a1 = 0.f;
    for (int e = beg + lane; e < end; e += 32) {
        float2 zv = g_z[g_csrc[e]];
        a0 += zv.x;
        a1 += zv.y;
    }
#pragma unroll
    for (int o = 16; o; o >>= 1) {
        a0 += __shfl_xor_sync(0xffffffffu, a0, o);
        a1 += __shfl_xor_sync(0xffffffffu, a1, o);
    }
    if (lane == 0) {
        float dii = g_dinv[i];
        float2 zi = g_z[i];
        float o0 = fmaf(a0 + zi.x, dii, b2[0]);
        float o1 = fmaf(a1 + zi.y, dii, b2[1]);
        float m   = fmaxf(o0, o1);
        float lse = m + log1pf(expf(fminf(o0, o1) - m));
        out[2 * i + 0] = o0 - lse;
        out[2 * i + 1] = o1 - lse;
    }
}

// ---------------- launch: fork GEMM onto side stream -------------------------
extern "C" void kernel_launch(void* const* d_in, const int* in_sizes, int n_in,
                              void* d_out, int out_size) {
    const float* x  = (const float*)d_in[0];
    const void*  ei = (const void*)d_in[1];
    const float* W1 = (const float*)d_in[2];
    const float* b1 = (const float*)d_in[3];
    const float* W2 = (const float*)d_in[4];
    const float* b2 = (const float*)d_in[5];
    float*       out = (float*)d_out;

    int N = in_sizes[0] / INF;
    int E = in_sizes[1] / 2;
    if (N > NMAX) N = NMAX;
    if (E > EMAX) E = EMAX;
    int NB = (N + 1023) / 1024;

    static cudaStream_t sG = (cudaStream_t)0;
    static cudaEvent_t  evA = (cudaEvent_t)0, evB = (cudaEvent_t)0;
    static void* p_cnt = 0;
    static int   inited = 0;
    if (!inited) {
        cudaGetSymbolAddress(&p_cnt, g_cnt);
        if (cudaStreamCreateWithFlags(&sG, cudaStreamNonBlocking) != cudaSuccess) sG = 0;
        if (sG) {
            cudaEventCreateWithFlags(&evA, cudaEventDisableTiming);
            cudaEventCreateWithFlags(&evB, cudaEventDisableTiming);
        }
        inited = 1;
    }

    bool fork = (sG != 0);
    if (fork) {
        cudaEventRecord(evA, 0);
        cudaStreamWaitEvent(sG, evA, 0);
        k_gemm1<<<(N + 127) / 128, 128, 0, sG>>>(x, W1, N);
        cudaEventRecord(evB, sG);
    }

    k_sniff<<<1, 256>>>((const unsigned int*)ei);
    cudaMemsetAsync(p_cnt, 0, (size_t)N * sizeof(int), 0);
    k_prep<<<(E + 255) / 256, 256>>>(ei, E);
    k_scan1<<<NB, 1024>>>(N);
    k_scan2<<<1, 128>>>(NB);
    k_scan3<<<NB, 1024>>>(N, E);
    k_fill<<<(E + 255) / 256, 256>>>(ei, E);

    if (fork) {
        cudaStreamWaitEvent(0, evB, 0);
    } else {
        k_gemm1<<<(N + 127) / 128, 128>>>(x, W1, N);
    }

    int agg_blocks = (N * 32 + 255) / 256;
    k_agg1<<<agg_blocks, 256>>>(b1, W2, N);
    k_agg2<<<agg_blocks, 256>>>(b2, out, N);
}

// round 5
// speedup vs baseline: 1.2786x; 1.0789x over previous
#include <cuda_runtime.h>
#include <cuda_fp16.h>

#define NMAX  100000
#define EMAX  3200000
#define INF   128
#define HID   50
#define PITCH 64          // halves per row: 128B-aligned rows, 1 line per gather
#define KC    16

// ---------------- static device scratch ----------------
__device__ int    g_is64;
__device__ int    g_cnt[NMAX];
__device__ int    g_off[NMAX + 1];
__device__ int    g_wcur[NMAX];
__device__ int    g_bsum[128];
__device__ int    g_csrc[EMAX];
__device__ float  g_dinv[NMAX];
__device__ __align__(128) __half g_h1h[(size_t)NMAX * PITCH]; // fp16, h1' = dinv*(x@W1)
__device__ float2 g_z[NMAX];                                  // z' = dinv*(h@W2)

// ---------------- dtype sniff ----------------
__global__ void k_sniff(const unsigned int* __restrict__ p) {
    __shared__ int nz;
    int t = threadIdx.x;
    if (t == 0) nz = 0;
    __syncthreads();
    if (p[2 * t + 1] != 0u) atomicOr(&nz, 1);
    __syncthreads();
    if (t == 0) g_is64 = nz ? 0 : 1;
}

// ---------------- count degrees (dst half only) ----------------
__global__ void k_prep(const void* __restrict__ eiv, int E) {
    int i = blockIdx.x * blockDim.x + threadIdx.x;
    if (i >= E) return;
    int d;
    if (g_is64) d = (int)((const long long*)eiv)[(size_t)E + i];
    else        d = ((const int*)eiv)[(size_t)E + i];
    atomicAdd(&g_cnt[d], 1);
}

// ---------------- warp-shuffle exclusive scan ----------------
__global__ void k_scan1(int N) {
    __shared__ int wsum[32];
    int t = threadIdx.x;
    int i = blockIdx.x * 1024 + t;
    int v = (i < N) ? g_cnt[i] : 0;
    int x = v;
#pragma unroll
    for (int o = 1; o < 32; o <<= 1) {
        int y = __shfl_up_sync(0xffffffffu, x, o);
        if ((t & 31) >= o) x += y;
    }
    if ((t & 31) == 31) wsum[t >> 5] = x;
    __syncthreads();
    if (t < 32) {
        int w = wsum[t], xx = w;
#pragma unroll
        for (int o = 1; o < 32; o <<= 1) {
            int y = __shfl_up_sync(0xffffffffu, xx, o);
            if (t >= o) xx += y;
        }
        wsum[t] = xx - w;
    }
    __syncthreads();
    int incl = x + wsum[t >> 5];
    if (i < N) g_off[i] = incl - v;
    if (t == 1023) g_bsum[blockIdx.x] = incl;
}

__global__ void k_scan2(int NB) {
    int t = threadIdx.x;
    __shared__ int wsum[4];
    int v = (t < NB) ? g_bsum[t] : 0;
    int x = v;
#pragma unroll
    for (int o = 1; o < 32; o <<= 1) {
        int y = __shfl_up_sync(0xffffffffu, x, o);
        if ((t & 31) >= o) x += y;
    }
    if ((t & 31) == 31) wsum[t >> 5] = x;
    __syncthreads();
    int base = 0;
    for (int w = 0; w < (t >> 5); w++) base += wsum[w];
    if (t < NB) g_bsum[t] = base + x - v;
}

__global__ void k_scan3(int N, int E) {
    int t = threadIdx.x;
    int i = blockIdx.x * 1024 + t;
    if (i >= N) return;
    int off = g_off[i] + g_bsum[blockIdx.x];
    g_off[i]  = off;
    g_wcur[i] = off;
    g_dinv[i] = rsqrtf((float)(g_cnt[i] + 1));
    if (i == 0) g_off[N] = E;
}

// ---------------- CSR fill ----------------
__global__ void k_fill(const void* __restrict__ eiv, int E) {
    int i = blockIdx.x * blockDim.x + threadIdx.x;
    if (i >= E) return;
    int s, d;
    if (g_is64) {
        const long long* p = (const long long*)eiv;
        s = (int)p[i];
        d = (int)p[(size_t)E + i];
    } else {
        const int* p = (const int*)eiv;
        s = p[i];
        d = p[(size_t)E + i];
    }
    int pos = atomicAdd(&g_wcur[d], 1);
    g_csrc[pos] = s;
}

// ---------------- GEMM1: h1' = dinv * (x @ W1), fp16 (waits on scan3) --------
__global__ void k_gemm1(const float* __restrict__ x, const float* __restrict__ W1, int N) {
    __shared__ float xs[128][KC + 1];
    __shared__ float Ws[KC][52];
    int tid   = threadIdx.x;
    int node0 = blockIdx.x * 128;
    int jg = tid & 3;
    int ng = tid >> 2;

    float acc[4][13];
#pragma unroll
    for (int m = 0; m < 4; m++)
#pragma unroll
        for (int jj = 0; jj < 13; jj++) acc[m][jj] = 0.f;

    for (int k0 = 0; k0 < INF; k0 += KC) {
        for (int i = tid; i < KC * 52; i += 128) {
            int kk = i / 52, j = i % 52;
            Ws[kk][j] = (j < HID) ? W1[(k0 + kk) * HID + j] : 0.f;
        }
#pragma unroll
        for (int r = 0; r < 4; r++) {
            int idx = tid + r * 128;
            int row = idx >> 2, c4 = idx & 3;
            int node = node0 + row;
            float4 v = make_float4(0.f, 0.f, 0.f, 0.f);
            if (node < N)
                v = *(const float4*)(x + (size_t)node * INF + k0 + c4 * 4);
            xs[row][c4 * 4 + 0] = v.x;
            xs[row][c4 * 4 + 1] = v.y;
            xs[row][c4 * 4 + 2] = v.z;
            xs[row][c4 * 4 + 3] = v.w;
        }
        __syncthreads();
#pragma unroll
        for (int kk = 0; kk < KC; kk++) {
            float xm[4];
#pragma unroll
            for (int m = 0; m < 4; m++) xm[m] = xs[ng * 4 + m][kk];
            float wv[13];
#pragma unroll
            for (int jj = 0; jj < 13; jj++) wv[jj] = Ws[kk][jg * 13 + jj];
#pragma unroll
            for (int m = 0; m < 4; m++)
#pragma unroll
                for (int jj = 0; jj < 13; jj++) acc[m][jj] += xm[m] * wv[jj];
        }
        __syncthreads();
    }
#pragma unroll
    for (int m = 0; m < 4; m++) {
        int node = node0 + ng * 4 + m;
        if (node < N) {
            float di = g_dinv[node];
#pragma unroll
            for (int jj = 0; jj < 13; jj++)
                g_h1h[(size_t)node * PITCH + jg * 13 + jj] = __float2half(acc[m][jj] * di);
        }
    }
}

// ---------------- layer-1 agg: pure adds over prescaled rows -----------------
__global__ void k_agg1(const float* __restrict__ b1, const float* __restrict__ W2, int N) {
    int gt = blockIdx.x * blockDim.x + threadIdx.x;
    int i = gt >> 5, lane = gt & 31;
    if (i >= N) return;

    float dii = g_dinv[i];
    int beg = g_off[i], end = g_off[i + 1];

    bool act = lane < 25;
    int  f   = lane * 2;
    const __half* hbase = g_h1h;
    float ax = 0.f, ay = 0.f;
    if (act) {
        float2 v = __half22float2(*(const __half2*)(hbase + ((size_t)i << 6) + f));
        ax = v.x; ay = v.y;                 // self term h1'[i]
    }
    int e = beg;
    for (; e + 8 <= end; e += 8) {
        int s0 = g_csrc[e + 0], s1 = g_csrc[e + 1];
        int s2 = g_csrc[e + 2], s3 = g_csrc[e + 3];
        int s4 = g_csrc[e + 4], s5 = g_csrc[e + 5];
        int s6 = g_csrc[e + 6], s7 = g_csrc[e + 7];
        if (act) {
            float2 v0 = __half22float2(*(const __half2*)(hbase + ((size_t)s0 << 6) + f));
            float2 v1 = __half22float2(*(const __half2*)(hbase + ((size_t)s1 << 6) + f));
            float2 v2 = __half22float2(*(const __half2*)(hbase + ((size_t)s2 << 6) + f));
            float2 v3 = __half22float2(*(const __half2*)(hbase + ((size_t)s3 << 6) + f));
            float2 v4 = __half22float2(*(const __half2*)(hbase + ((size_t)s4 << 6) + f));
            float2 v5 = __half22float2(*(const __half2*)(hbase + ((size_t)s5 << 6) + f));
            float2 v6 = __half22float2(*(const __half2*)(hbase + ((size_t)s6 << 6) + f));
            float2 v7 = __half22float2(*(const __half2*)(hbase + ((size_t)s7 << 6) + f));
            ax += (v0.x + v1.x) + (v2.x + v3.x) + ((v4.x + v5.x) + (v6.x + v7.x));
            ay += (v0.y + v1.y) + (v2.y + v3.y) + ((v4.y + v5.y) + (v6.y + v7.y));
        }
    }
    for (; e < end; e++) {
        int s0 = g_csrc[e];
        if (act) {
            float2 v0 = __half22float2(*(const __half2*)(hbase + ((size_t)s0 << 6) + f));
            ax += v0.x;
            ay += v0.y;
        }
    }
    float z0 = 0.f, z1 = 0.f;
    if (act) {
        float2 bb = *(const float2*)(b1 + f);
        float hx = fmaxf(fmaf(ax, dii, bb.x), 0.f);
        float hy = fmaxf(fmaf(ay, dii, bb.y), 0.f);
        float4 w = *(const float4*)(W2 + 2 * f);
        z0 = hx * w.x + hy * w.z;
        z1 = hx * w.y + hy * w.w;
    }
#pragma unroll
    for (int o = 16; o; o >>= 1) {
        z0 += __shfl_xor_sync(0xffffffffu, z0, o);
        z1 += __shfl_xor_sync(0xffffffffu, z1, o);
    }
    if (lane == 0) g_z[i] = make_float2(z0 * dii, z1 * dii);
}

// ---------------- layer-2 agg + log_softmax ----------------------------------
__global__ void k_agg2(const float* __restrict__ b2, float* __restrict__ out, int N) {
    int gt = blockIdx.x * blockDim.x + threadIdx.x;
    int i = gt >> 5, lane = gt & 31;
    if (i >= N) return;

    int beg = g_off[i], end = g_off[i + 1];
    float a0 = 0.f, a1 = 0.f;
    for (int e = beg + lane; e < end; e += 32) {
        float2 zv = g_z[g_csrc[e]];
        a0 += zv.x;
        a1 += zv.y;
    }
#pragma unroll
    for (int o = 16; o; o >>= 1) {
        a0 += __shfl_xor_sync(0xffffffffu, a0, o);
        a1 += __shfl_xor_sync(0xffffffffu, a1, o);
    }
    if (lane == 0) {
        float dii = g_dinv[i];
        float2 zi = g_z[i];
        float o0 = fmaf(a0 + zi.x, dii, b2[0]);
        float o1 = fmaf(a1 + zi.y, dii, b2[1]);
        float m   = fmaxf(o0, o1);
        float lse = m + log1pf(expf(fminf(o0, o1) - m));
        out[2 * i + 0] = o0 - lse;
        out[2 * i + 1] = o1 - lse;
    }
}

// ---------------- launch: GEMM on side stream after scan3 --------------------
extern "C" void kernel_launch(void* const* d_in, const int* in_sizes, int n_in,
                              void* d_out, int out_size) {
    const float* x  = (const float*)d_in[0];
    const void*  ei = (const void*)d_in[1];
    const float* W1 = (const float*)d_in[2];
    const float* b1 = (const float*)d_in[3];
    const float* W2 = (const float*)d_in[4];
    const float* b2 = (const float*)d_in[5];
    float*       out = (float*)d_out;

    int N = in_sizes[0] / INF;
    int E = in_sizes[1] / 2;
    if (N > NMAX) N = NMAX;
    if (E > EMAX) E = EMAX;
    int NB = (N + 1023) / 1024;

    static cudaStream_t sG = (cudaStream_t)0;
    static cudaEvent_t  evS3 = (cudaEvent_t)0, evB = (cudaEvent_t)0;
    static void* p_cnt = 0;
    static int   inited = 0;
    if (!inited) {
        cudaGetSymbolAddress(&p_cnt, g_cnt);
        if (cudaStreamCreateWithFlags(&sG, cudaStreamNonBlocking) != cudaSuccess) sG = 0;
        if (sG) {
            cudaEventCreateWithFlags(&evS3, cudaEventDisableTiming);
            cudaEventCreateWithFlags(&evB, cudaEventDisableTiming);
        }
        inited = 1;
    }
    bool fork = (sG != 0);

    k_sniff<<<1, 256>>>((const unsigned int*)ei);
    cudaMemsetAsync(p_cnt, 0, (size_t)N * sizeof(int), 0);
    k_prep<<<(E + 255) / 256, 256>>>(ei, E);
    k_scan1<<<NB, 1024>>>(N);
    k_scan2<<<1, 128>>>(NB);
    k_scan3<<<NB, 1024>>>(N, E);

    if (fork) {
        cudaEventRecord(evS3, 0);
        cudaStreamWaitEvent(sG, evS3, 0);
        k_gemm1<<<(N + 127) / 128, 128, 0, sG>>>(x, W1, N);   // overlaps k_fill
        cudaEventRecord(evB, sG);
    }

    k_fill<<<(E + 255) / 256, 256>>>(ei, E);

    if (fork) {
        cudaStreamWaitEvent(0, evB, 0);
    } else {
        k_gemm1<<<(N + 127) / 128, 128>>>(x, W1, N);
    }

    int agg_blocks = (N * 32 + 255) / 256;
    k_agg1<<<agg_blocks, 256>>>(b1, W2, N);
    k_agg2<<<agg_blocks, 256>>>(b2, out, N);
}